// round 15
// baseline (speedup 1.0000x reference)
#include <cuda_runtime.h>
#include <cuda_bf16.h>
#include <cuda_fp16.h>
#include <math.h>
#include <stdint.h>

#define SEQ   512
#define BATCH 64
#define DIN   1024
#define DLAT  1024
#define DCAT  2048
#define NGATE 4096

// ---------------- device scratch ----------------
__device__ float g_gx[(size_t)SEQ * BATCH * NGATE];   // x-side gates (+bias)
__device__ __half g_wr[(size_t)NGATE * DLAT];         // recurrent W fp16, wrow = j*4+gate
__device__ __half g_wx[(size_t)NGATE * DIN];          // x-part W, fp16 single
__device__ __half g_xh[(size_t)SEQ * BATCH * DIN];    // x fp16 (single)
__device__ __half g_h2[2][BATCH * DLAT];              // double-buffered h fp16 (single)
__device__ unsigned g_flags[128];
__device__ unsigned g_epoch2;

__device__ __forceinline__ float sigmoidf_(float x) {
    return __fdividef(1.0f, 1.0f + __expf(-x));
}
__device__ __forceinline__ float tanhf_(float x) {
    float e = __expf(2.0f * x);
    return 1.0f - __fdividef(2.0f, e + 1.0f);
}

__device__ __forceinline__ uint32_t smem_u32(const void* p) {
    uint32_t a;
    asm("{ .reg .u64 t; cvta.to.shared.u64 t, %1; cvt.u32.u64 %0, t; }" : "=r"(a) : "l"(p));
    return a;
}

#define CP16(dst, src) \
    asm volatile("cp.async.cg.shared.global [%0], [%1], 16;" :: "r"(dst), "l"(src))
#define CP_COMMIT() asm volatile("cp.async.commit_group;")
#define CP_WAIT(N)  asm volatile("cp.async.wait_group %0;" :: "n"(N))

__device__ __forceinline__ void mma_f16(float c[4], uint32_t a0, uint32_t a1,
                                        uint32_t a2, uint32_t a3,
                                        uint32_t b0, uint32_t b1) {
    asm volatile("mma.sync.aligned.m16n8k16.row.col.f32.f16.f16.f32 "
        "{%0,%1,%2,%3}, {%4,%5,%6,%7}, {%8,%9}, {%0,%1,%2,%3};"
        : "+f"(c[0]), "+f"(c[1]), "+f"(c[2]), "+f"(c[3])
        : "r"(a0), "r"(a1), "r"(a2), "r"(a3), "r"(b0), "r"(b1));
}

__device__ __forceinline__ unsigned ld_acq(const unsigned* p) {
    unsigned v;
    asm volatile("ld.acquire.gpu.global.u32 %0, [%1];" : "=r"(v) : "l"(p));
    return v;
}
__device__ __forceinline__ void st_rel(unsigned* p, unsigned v) {
    asm volatile("st.release.gpu.global.u32 [%0], %1;" :: "l"(p), "r"(v) : "memory");
}

#define LDSM_X4(d0, d1, d2, d3, a) \
    asm volatile("ldmatrix.sync.aligned.m8n8.x4.shared.b16 {%0,%1,%2,%3}, [%4];" \
        : "=r"(d0), "=r"(d1), "=r"(d2), "=r"(d3) : "r"(a))

// ---------------------------------------------------------------
__global__ void init_state() {
    int i = blockIdx.x * blockDim.x + threadIdx.x;
    if (i < BATCH * DLAT) {
        g_h2[0][i] = __float2half(0.0f);
    }
    if (i < 128) g_flags[i] = 0;
    if (i == 0) g_epoch2 = 0;
}

// Split W: recurrent part (k<1024) -> fp16 single (wrow-major); x part -> fp16 single.
__global__ void wsplit_build(const float* __restrict__ Wf, const float* __restrict__ Wi,
                             const float* __restrict__ Wo, const float* __restrict__ Wc) {
    int idx = blockIdx.x * blockDim.x + threadIdx.x;   // over 4096*2048
    int n = idx >> 11, k2 = idx & 2047;
    int gate = n >> 10, j = n & 1023;
    const float* W = (gate == 0) ? Wf : (gate == 1) ? Wi : (gate == 2) ? Wo : Wc;
    float v = W[(size_t)j * DCAT + k2];
    if (k2 < 1024) {
        int wrow = j * 4 + gate;
        g_wr[(size_t)wrow * DLAT + k2] = __float2half(v);
    } else {
        g_wx[(size_t)n * DIN + (k2 - 1024)] = __float2half(v);
    }
}

// Convert x to fp16 (single)
__global__ void xsplit_build(const float* __restrict__ x) {
    size_t i4 = (size_t)blockIdx.x * blockDim.x + threadIdx.x;
    float4 v = ((const float4*)x)[i4];
    size_t b = i4 * 4;
    g_xh[b + 0] = __float2half(v.x);
    g_xh[b + 1] = __float2half(v.y);
    g_xh[b + 2] = __float2half(v.z);
    g_xh[b + 3] = __float2half(v.w);
}

// ---------------------------------------------------------------
// Phase A: gx = x @ Wx^T + b, fp16 single HMMA, ldmatrix frag loads.
// Block 128m x 128n x BK64, 256 thr (8 warps = 2m x 4n).
// ---------------------------------------------------------------
#define IA_PART  18432
#define IA_BUF   36864
#define IA_DSMEM 73728

__global__ void __launch_bounds__(256) input_hmma(
    const float* __restrict__ bf, const float* __restrict__ bi,
    const float* __restrict__ bo, const float* __restrict__ bc)
{
    extern __shared__ __align__(16) uint8_t dsm[];
    __shared__ float sbias[128];
    const uint32_t sb = smem_u32(dsm);

    const int tid  = threadIdx.x;
    const int lane = tid & 31;
    const int wid  = tid >> 5;
    const int wm   = wid & 1;
    const int wn   = wid >> 1;
    const int gid  = lane >> 2;
    const int tig  = lane & 3;
    const uint32_t lrow  = (uint32_t)(lane & 15);
    const uint32_t khalf = (uint32_t)((lane >> 4) & 1) * 16;

    const int n0g = blockIdx.x * 128;
    const int m0g = blockIdx.y * 128;

    if (tid < 128) {
        int gate = n0g >> 10;
        const float* bsrc = (gate == 0) ? bf : (gate == 1) ? bi : (gate == 2) ? bo : bc;
        sbias[tid] = bsrc[(n0g & 1023) + tid];
    }

    #define IA_FILL(BUF, C) do {                                                 \
        _Pragma("unroll")                                                        \
        for (int i = 0; i < 8; i++) {                                            \
            int e = tid + i * 256;                                               \
            int part = e >> 10, rem = e & 1023;                                  \
            int row = rem >> 3, seg = rem & 7;                                   \
            const __half* src = part                                             \
                ? g_wx + (size_t)(n0g + row) * DIN + (C) * 64 + seg * 8          \
                : g_xh + (size_t)(m0g + row) * DIN + (C) * 64 + seg * 8;         \
            CP16(sb + (BUF) * IA_BUF + part * IA_PART + row * 144 + seg * 16, src); \
        }                                                                        \
        CP_COMMIT();                                                             \
    } while (0)

    float acc[4][4][4];
    #pragma unroll
    for (int t = 0; t < 4; t++)
        #pragma unroll
        for (int u = 0; u < 4; u++)
            #pragma unroll
            for (int i = 0; i < 4; i++) acc[t][u][i] = 0.0f;

    IA_FILL(0, 0);
    IA_FILL(1, 1);

    #pragma unroll 1
    for (int c = 0; c < 16; c++) {
        if (c + 2 < 16) CP_WAIT(1); else CP_WAIT(0);
        __syncthreads();
        const uint32_t base = sb + (c & 1) * IA_BUF;

        #pragma unroll
        for (int q = 0; q < 4; q++) {
            uint32_t aH[4][4];
            #pragma unroll
            for (int t = 0; t < 4; t++) {
                uint32_t aq = base + (wm * 64 + t * 16 + lrow) * 144 + khalf
                            + (uint32_t)q * 32;
                LDSM_X4(aH[t][0], aH[t][1], aH[t][2], aH[t][3], aq);
            }
            #pragma unroll
            for (int g = 0; g < 2; g++) {
                uint32_t b0, b1, b2, b3;
                uint32_t bq = base + IA_PART
                            + (wn * 32 + g * 16 + lrow) * 144 + khalf
                            + (uint32_t)q * 32;
                LDSM_X4(b0, b1, b2, b3, bq);
                #pragma unroll
                for (int t = 0; t < 4; t++) {
                    mma_f16(acc[t][2 * g + 0], aH[t][0], aH[t][1], aH[t][2], aH[t][3], b0, b2);
                    mma_f16(acc[t][2 * g + 1], aH[t][0], aH[t][1], aH[t][2], aH[t][3], b1, b3);
                }
            }
        }
        __syncthreads();
        if (c + 2 < 16) IA_FILL(c & 1, c + 2);
    }

    #pragma unroll
    for (int t = 0; t < 4; t++) {
        const int row = m0g + wm * 64 + t * 16 + gid;
        #pragma unroll
        for (int u = 0; u < 4; u++) {
            const int cl = wn * 32 + u * 8 + tig * 2;
            const int col = n0g + cl;
            float b0 = sbias[cl], b1 = sbias[cl + 1];
            float2 v01 = make_float2(acc[t][u][0] + b0, acc[t][u][1] + b1);
            float2 v23 = make_float2(acc[t][u][2] + b0, acc[t][u][3] + b1);
            *(float2*)&g_gx[(size_t)row * NGATE + col]       = v01;
            *(float2*)&g_gx[(size_t)(row + 8) * NGATE + col] = v23;
        }
    }
}

// ---------------------------------------------------------------
// Phase B: PERSISTENT weight-resident HMMA kernel.
// fp16 W (resident, 66 KB) x fp16 h. Per step: all 8 h-chunks (16 KB each)
// issued as cp.async immediately after the barrier into 8 RESIDENT buffers
// (no reuse within a step -> one sync per chunk, max MLP at barrier exit).
// Warp decomposition 2m x 2n x 2kg, ldmatrix.x4, kg-partials in smem
// (reduction scratch overlaps dead B buffers 0-1). Two-hop grid barrier.
// ---------------------------------------------------------------
#define WROW      2064             // 1024 fp16 + 16B pad
#define BBASE     66048            // 32 * WROW
#define BROW      272
#define BBUF      17408            // 64 * BROW (one chunk)
#define GXBASE    205312           // BBASE + 8*BBUF
#define DSMEM_BYTES 214528         // GXBASE + 9216 (red overlaps B bufs 0-1)

__global__ void __launch_bounds__(256, 1) lstm_persistent(float* __restrict__ out)
{
    extern __shared__ __align__(16) uint8_t dsm[];
    const uint32_t sb = smem_u32(dsm);

    const int tid  = threadIdx.x;
    const int lane = tid & 31;
    const int wid  = tid >> 5;
    const int wm   = wid & 1;          // m half (16 gate-rows)
    const int wn   = (wid >> 1) & 1;   // batch half (n32)
    const int kg   = wid >> 2;         // k half within chunk (64k)
    const int gid  = lane >> 2;
    const int tig  = lane & 3;

    const int r0 = blockIdx.x * 32;    // wrow base
    const int jb = blockIdx.x * 8;     // latent base

    // ---- load resident W slice (fp16 single, 64 KB) ----
    #pragma unroll
    for (int i = 0; i < 16; i++) {
        int e = tid + i * 256;             // 4096 x 16B
        int row = e >> 7, seg = e & 127;
        const __half* src = g_wr + (size_t)(r0 + row) * DLAT + seg * 8;
        CP16(sb + row * WROW + seg * 16, src);
    }
    CP_COMMIT();

    #define GX_PREF(T) do {                                                      \
        const float* gxt = g_gx + (size_t)(T) * BATCH * NGATE;                   \
        _Pragma("unroll")                                                        \
        for (int i = 0; i < 2; i++) {                                            \
            int e = tid + i * 256;                                               \
            int m = e >> 3, g = (e >> 1) & 3, half = e & 1;                      \
            const float* src = gxt + (size_t)m * NGATE + g * 1024 + jb + half * 4; \
            CP16(sb + GXBASE + m * 144 + g * 32 + half * 16, src);               \
        }                                                                        \
        CP_COMMIT();                                                             \
    } while (0)

    GX_PREF(0);
    CP_WAIT(0);
    __syncthreads();

    // ldmatrix lane-row pattern (A and B): lane&15 row, lane>>4 k-half
    const uint32_t lrow   = (uint32_t)(lane & 15);
    const uint32_t khalf  = (uint32_t)((lane >> 4) & 1) * 16;
    const uint32_t abase  = sb + (wm * 16 + lrow) * WROW + khalf;      // + k*2
    const uint32_t bbase0 = (wn * 32 + lrow) * BROW + khalf;           // group g: +g*16*BROW

    // epilogue ownership: cell pair (em, jb+ejl), (em, jb+ejl+1)
    const int em  = tid >> 2;
    const int ejl = (tid & 3) * 2;

    float creg[2] = {0.0f, 0.0f};
    float* red = (float*)(dsm + BBASE);            // overlaps B bufs 0-1 (dead at use)
    const float* gxs = (const float*)(dsm + GXBASE);

    for (int t = 0; t < SEQ; t++) {
        // ---- grid barrier (flags + block0 aggregator + epoch) ----
        if (t > 0) {
            if (tid == 0) st_rel(&g_flags[blockIdx.x], (unsigned)t);
            if (blockIdx.x == 0) {
                if (tid < 128) {
                    while (ld_acq(&g_flags[tid]) < (unsigned)t) {}
                }
                __syncthreads();
                if (tid == 0) st_rel(&g_epoch2, (unsigned)t);
            }
            if (tid == 0) {
                while (ld_acq(&g_epoch2) < (unsigned)t) {}
            }
            __syncthreads();
        }

        const int rb = t & 1;
        const __half* hsrc = g_h2[rb];

        // fill chunk C (128 k) into resident buf C: 4 CP16/thread
        #define FILL_B(C) do {                                                   \
            _Pragma("unroll")                                                    \
            for (int i = 0; i < 4; i++) {                                        \
                int e = tid + i * 256;                                           \
                int row = e >> 4, seg = e & 15;                                  \
                const __half* src = hsrc + (size_t)row * DLAT + (C) * 128 + seg * 8; \
                CP16(sb + BBASE + (C) * BBUF + row * BROW + seg * 16, src);      \
            }                                                                    \
            CP_COMMIT();                                                         \
        } while (0)

        // issue ALL chunks right after the barrier (max MLP)
        FILL_B(0); FILL_B(1); FILL_B(2); FILL_B(3);
        FILL_B(4); FILL_B(5); FILL_B(6); FILL_B(7);

        float aH[4][4];
        #pragma unroll
        for (int nt = 0; nt < 4; nt++)
            #pragma unroll
            for (int i = 0; i < 4; i++) aH[nt][i] = 0.f;

        #pragma unroll
        for (int c = 0; c < 8; c++) {
            // pending groups allowed = fills not yet needed (gx(t+1) group from
            // last iteration completed before chunk-0 wait via count 7)
            if      (c == 0) CP_WAIT(7);
            else if (c == 1) CP_WAIT(6);
            else if (c == 2) CP_WAIT(5);
            else if (c == 3) CP_WAIT(4);
            else if (c == 4) CP_WAIT(3);
            else if (c == 5) CP_WAIT(2);
            else if (c == 6) CP_WAIT(1);
            else             CP_WAIT(0);
            __syncthreads();

            const uint32_t bB = sb + BBASE + (uint32_t)c * BBUF + bbase0;
            const uint32_t kA = (uint32_t)(c * 128 + kg * 64) * 2;   // A byte k-offset
            const uint32_t kB = (uint32_t)(kg * 64) * 2;             // B byte k-offset in chunk

            #pragma unroll
            for (int q = 0; q < 4; q++) {
                uint32_t aw0, aw1, aw2, aw3;
                const uint32_t aq = abase + kA + (uint32_t)q * 32;
                LDSM_X4(aw0, aw1, aw2, aw3, aq);

                #pragma unroll
                for (int g = 0; g < 2; g++) {
                    uint32_t bh0, bh1, bh2, bh3;
                    const uint32_t bq = bB + (uint32_t)g * 16 * BROW + kB + (uint32_t)q * 32;
                    LDSM_X4(bh0, bh1, bh2, bh3, bq);
                    mma_f16(aH[2 * g + 0], aw0, aw1, aw2, aw3, bh0, bh2);
                    mma_f16(aH[2 * g + 1], aw0, aw1, aw2, aw3, bh1, bh3);
                }
            }
        }

        // ---- stage kg-partials to smem scratch [kg][32 rows][66] ----
        // (bufs 0-1 are dead: every warp is past chunk 6's sync)
        #pragma unroll
        for (int nt = 0; nt < 4; nt++) {
            int R0 = wm * 16 + gid;
            int C  = wn * 32 + nt * 8 + tig * 2;
            *(float2*)&red[kg * 2112 + R0 * 66 + C]       = make_float2(aH[nt][0], aH[nt][1]);
            *(float2*)&red[kg * 2112 + (R0 + 8) * 66 + C] = make_float2(aH[nt][2], aH[nt][3]);
        }
        __syncthreads();

        // ---- fused epilogue: 2 cells per thread ----
        const int rb2 = rb ^ 1;
        __half* hw = g_h2[rb2];
        float hval[2];
        #pragma unroll
        for (int p = 0; p < 2; p++) {
            const int jl = ejl + p;
            const int rr = jl * 4;
            float sf = red[(rr + 0) * 66 + em] + red[2112 + (rr + 0) * 66 + em];
            float si = red[(rr + 1) * 66 + em] + red[2112 + (rr + 1) * 66 + em];
            float so = red[(rr + 2) * 66 + em] + red[2112 + (rr + 2) * 66 + em];
            float sg = red[(rr + 3) * 66 + em] + red[2112 + (rr + 3) * 66 + em];
            float vf = sigmoidf_(sf + gxs[em * 36 + 0 * 8 + jl]);
            float vi = sigmoidf_(si + gxs[em * 36 + 1 * 8 + jl]);
            float vo = sigmoidf_(so + gxs[em * 36 + 2 * 8 + jl]);
            float vg = tanhf_(sg + gxs[em * 36 + 3 * 8 + jl]);
            float cc = vf * creg[p] + vi * vg;
            creg[p] = cc;
            float h = vo * tanhf_(cc);
            hval[p] = h;
            const int j = jb + jl;
            hw[(size_t)em * DLAT + j] = __float2half(h);
        }
        *(float2*)&out[((size_t)t * BATCH + em) * DLAT + jb + ejl] =
            make_float2(hval[0], hval[1]);

        __syncthreads();
        if (t + 1 < SEQ) GX_PREF(t + 1);
    }
}

// ---------------------------------------------------------------
extern "C" void kernel_launch(void* const* d_in, const int* in_sizes, int n_in,
                              void* d_out, int out_size)
{
    const float* x  = (const float*)d_in[0];
    const float* Wf = (const float*)d_in[1];
    const float* bf = (const float*)d_in[2];
    const float* Wi = (const float*)d_in[3];
    const float* bi = (const float*)d_in[4];
    const float* Wo = (const float*)d_in[5];
    const float* bo = (const float*)d_in[6];
    const float* Wc = (const float*)d_in[7];
    const float* bc = (const float*)d_in[8];
    float* out = (float*)d_out;

    cudaFuncSetAttribute(input_hmma, cudaFuncAttributeMaxDynamicSharedMemorySize,
                         IA_DSMEM);
    cudaFuncSetAttribute(lstm_persistent, cudaFuncAttributeMaxDynamicSharedMemorySize,
                         DSMEM_BYTES);

    init_state<<<256, 256>>>();
    wsplit_build<<<(NGATE * DCAT) / 256, 256>>>(Wf, Wi, Wo, Wc);
    xsplit_build<<<(SEQ * BATCH * DIN) / (4 * 256), 256>>>(x);

    dim3 gridA(NGATE / 128, (SEQ * BATCH) / 128);   // (32, 256)
    input_hmma<<<gridA, 256, IA_DSMEM>>>(bf, bi, bo, bc);

    lstm_persistent<<<128, 256, DSMEM_BYTES>>>(out);
}

// round 16
// speedup vs baseline: 1.3260x; 1.3260x over previous
#include <cuda_runtime.h>
#include <cuda_bf16.h>
#include <cuda_fp16.h>
#include <math.h>
#include <stdint.h>

#define SEQ   512
#define BATCH 64
#define DIN   1024
#define DLAT  1024
#define DCAT  2048
#define NGATE 4096

// ---------------- device scratch ----------------
__device__ float g_gx[(size_t)SEQ * BATCH * NGATE];   // x-side gates (+bias)
__device__ __half g_wr[(size_t)NGATE * DLAT];         // recurrent W fp16, wrow = j*4+gate
__device__ __half g_wx[(size_t)NGATE * DIN];          // x-part W, fp16 single
__device__ __half g_xh[(size_t)SEQ * BATCH * DIN];    // x fp16 (single)
__device__ __half g_h2[2][BATCH * DLAT];              // double-buffered h fp16 (single)
__device__ unsigned g_flags[128];
__device__ unsigned g_epoch2;

__device__ __forceinline__ float sigmoidf_(float x) {
    return __fdividef(1.0f, 1.0f + __expf(-x));
}
__device__ __forceinline__ float tanhf_(float x) {
    float e = __expf(2.0f * x);
    return 1.0f - __fdividef(2.0f, e + 1.0f);
}

__device__ __forceinline__ uint32_t smem_u32(const void* p) {
    uint32_t a;
    asm("{ .reg .u64 t; cvta.to.shared.u64 t, %1; cvt.u32.u64 %0, t; }" : "=r"(a) : "l"(p));
    return a;
}

#define CP16(dst, src) \
    asm volatile("cp.async.cg.shared.global [%0], [%1], 16;" :: "r"(dst), "l"(src))
#define CP_COMMIT() asm volatile("cp.async.commit_group;")
#define CP_WAIT(N)  asm volatile("cp.async.wait_group %0;" :: "n"(N))

__device__ __forceinline__ void mma_f16(float c[4], uint32_t a0, uint32_t a1,
                                        uint32_t a2, uint32_t a3,
                                        uint32_t b0, uint32_t b1) {
    asm volatile("mma.sync.aligned.m16n8k16.row.col.f32.f16.f16.f32 "
        "{%0,%1,%2,%3}, {%4,%5,%6,%7}, {%8,%9}, {%0,%1,%2,%3};"
        : "+f"(c[0]), "+f"(c[1]), "+f"(c[2]), "+f"(c[3])
        : "r"(a0), "r"(a1), "r"(a2), "r"(a3), "r"(b0), "r"(b1));
}

__device__ __forceinline__ unsigned ld_acq(const unsigned* p) {
    unsigned v;
    asm volatile("ld.acquire.gpu.global.u32 %0, [%1];" : "=r"(v) : "l"(p));
    return v;
}
__device__ __forceinline__ void st_rel(unsigned* p, unsigned v) {
    asm volatile("st.release.gpu.global.u32 [%0], %1;" :: "l"(p), "r"(v) : "memory");
}

#define LDSM_X4(d0, d1, d2, d3, a) \
    asm volatile("ldmatrix.sync.aligned.m8n8.x4.shared.b16 {%0,%1,%2,%3}, [%4];" \
        : "=r"(d0), "=r"(d1), "=r"(d2), "=r"(d3) : "r"(a))

// ---------------------------------------------------------------
__global__ void init_state() {
    int i = blockIdx.x * blockDim.x + threadIdx.x;
    if (i < BATCH * DLAT) {
        g_h2[0][i] = __float2half(0.0f);
    }
    if (i < 128) g_flags[i] = 0;
    if (i == 0) g_epoch2 = 0;
}

// Split W: recurrent part (k<1024) -> fp16 single (wrow-major); x part -> fp16 single.
__global__ void wsplit_build(const float* __restrict__ Wf, const float* __restrict__ Wi,
                             const float* __restrict__ Wo, const float* __restrict__ Wc) {
    int idx = blockIdx.x * blockDim.x + threadIdx.x;   // over 4096*2048
    int n = idx >> 11, k2 = idx & 2047;
    int gate = n >> 10, j = n & 1023;
    const float* W = (gate == 0) ? Wf : (gate == 1) ? Wi : (gate == 2) ? Wo : Wc;
    float v = W[(size_t)j * DCAT + k2];
    if (k2 < 1024) {
        int wrow = j * 4 + gate;
        g_wr[(size_t)wrow * DLAT + k2] = __float2half(v);
    } else {
        g_wx[(size_t)n * DIN + (k2 - 1024)] = __float2half(v);
    }
}

// Convert x to fp16 (single)
__global__ void xsplit_build(const float* __restrict__ x) {
    size_t i4 = (size_t)blockIdx.x * blockDim.x + threadIdx.x;
    float4 v = ((const float4*)x)[i4];
    size_t b = i4 * 4;
    g_xh[b + 0] = __float2half(v.x);
    g_xh[b + 1] = __float2half(v.y);
    g_xh[b + 2] = __float2half(v.z);
    g_xh[b + 3] = __float2half(v.w);
}

// ---------------------------------------------------------------
// Phase A: gx = x @ Wx^T + b, fp16 single HMMA, ldmatrix frag loads.
// Block 128m x 128n x BK64, 256 thr (8 warps = 2m x 4n).
// ---------------------------------------------------------------
#define IA_PART  18432
#define IA_BUF   36864
#define IA_DSMEM 73728

__global__ void __launch_bounds__(256) input_hmma(
    const float* __restrict__ bf, const float* __restrict__ bi,
    const float* __restrict__ bo, const float* __restrict__ bc)
{
    extern __shared__ __align__(16) uint8_t dsm[];
    __shared__ float sbias[128];
    const uint32_t sb = smem_u32(dsm);

    const int tid  = threadIdx.x;
    const int lane = tid & 31;
    const int wid  = tid >> 5;
    const int wm   = wid & 1;
    const int wn   = wid >> 1;
    const int gid  = lane >> 2;
    const int tig  = lane & 3;
    const uint32_t lrow  = (uint32_t)(lane & 15);
    const uint32_t khalf = (uint32_t)((lane >> 4) & 1) * 16;

    const int n0g = blockIdx.x * 128;
    const int m0g = blockIdx.y * 128;

    if (tid < 128) {
        int gate = n0g >> 10;
        const float* bsrc = (gate == 0) ? bf : (gate == 1) ? bi : (gate == 2) ? bo : bc;
        sbias[tid] = bsrc[(n0g & 1023) + tid];
    }

    #define IA_FILL(BUF, C) do {                                                 \
        _Pragma("unroll")                                                        \
        for (int i = 0; i < 8; i++) {                                            \
            int e = tid + i * 256;                                               \
            int part = e >> 10, rem = e & 1023;                                  \
            int row = rem >> 3, seg = rem & 7;                                   \
            const __half* src = part                                             \
                ? g_wx + (size_t)(n0g + row) * DIN + (C) * 64 + seg * 8          \
                : g_xh + (size_t)(m0g + row) * DIN + (C) * 64 + seg * 8;         \
            CP16(sb + (BUF) * IA_BUF + part * IA_PART + row * 144 + seg * 16, src); \
        }                                                                        \
        CP_COMMIT();                                                             \
    } while (0)

    float acc[4][4][4];
    #pragma unroll
    for (int t = 0; t < 4; t++)
        #pragma unroll
        for (int u = 0; u < 4; u++)
            #pragma unroll
            for (int i = 0; i < 4; i++) acc[t][u][i] = 0.0f;

    IA_FILL(0, 0);
    IA_FILL(1, 1);

    #pragma unroll 1
    for (int c = 0; c < 16; c++) {
        if (c + 2 < 16) CP_WAIT(1); else CP_WAIT(0);
        __syncthreads();
        const uint32_t base = sb + (c & 1) * IA_BUF;

        #pragma unroll
        for (int q = 0; q < 4; q++) {
            uint32_t aH[4][4];
            #pragma unroll
            for (int t = 0; t < 4; t++) {
                uint32_t aq = base + (wm * 64 + t * 16 + lrow) * 144 + khalf
                            + (uint32_t)q * 32;
                LDSM_X4(aH[t][0], aH[t][1], aH[t][2], aH[t][3], aq);
            }
            #pragma unroll
            for (int g = 0; g < 2; g++) {
                uint32_t b0, b1, b2, b3;
                uint32_t bq = base + IA_PART
                            + (wn * 32 + g * 16 + lrow) * 144 + khalf
                            + (uint32_t)q * 32;
                LDSM_X4(b0, b1, b2, b3, bq);
                #pragma unroll
                for (int t = 0; t < 4; t++) {
                    mma_f16(acc[t][2 * g + 0], aH[t][0], aH[t][1], aH[t][2], aH[t][3], b0, b2);
                    mma_f16(acc[t][2 * g + 1], aH[t][0], aH[t][1], aH[t][2], aH[t][3], b1, b3);
                }
            }
        }
        __syncthreads();
        if (c + 2 < 16) IA_FILL(c & 1, c + 2);
    }

    #pragma unroll
    for (int t = 0; t < 4; t++) {
        const int row = m0g + wm * 64 + t * 16 + gid;
        #pragma unroll
        for (int u = 0; u < 4; u++) {
            const int cl = wn * 32 + u * 8 + tig * 2;
            const int col = n0g + cl;
            float b0 = sbias[cl], b1 = sbias[cl + 1];
            float2 v01 = make_float2(acc[t][u][0] + b0, acc[t][u][1] + b1);
            float2 v23 = make_float2(acc[t][u][2] + b0, acc[t][u][3] + b1);
            *(float2*)&g_gx[(size_t)row * NGATE + col]       = v01;
            *(float2*)&g_gx[(size_t)(row + 8) * NGATE + col] = v23;
        }
    }
}

// ---------------------------------------------------------------
// Phase B: PERSISTENT weight-resident HMMA kernel (R13 structure, exact).
// fp16 W (resident, 66 KB) x fp16 h single, 4-deep rolling cp.async
// pipeline (16 KB/chunk). Warp decomposition 2m x 2n x 2kg, ldmatrix.x4,
// kg-partials in smem, two-hop flag/epoch grid barrier.
// ---------------------------------------------------------------
#define WROW      2064             // 1024 fp16 + 16B pad
#define BBASE     66048            // 32 * WROW
#define BROW      272
#define BBUF      17408            // 64 * BROW (one chunk)
#define GXBASE    135680           // BBASE + 4*BBUF
#define REDBASE   144896           // GXBASE + 9216
#define DSMEM_BYTES 161792         // REDBASE + 2*32*66*4

__global__ void __launch_bounds__(256, 1) lstm_persistent(float* __restrict__ out)
{
    extern __shared__ __align__(16) uint8_t dsm[];
    const uint32_t sb = smem_u32(dsm);

    const int tid  = threadIdx.x;
    const int lane = tid & 31;
    const int wid  = tid >> 5;
    const int wm   = wid & 1;          // m half (16 gate-rows)
    const int wn   = (wid >> 1) & 1;   // batch half (n32)
    const int kg   = wid >> 2;         // k half within chunk (64k)
    const int gid  = lane >> 2;
    const int tig  = lane & 3;

    const int r0 = blockIdx.x * 32;    // wrow base
    const int jb = blockIdx.x * 8;     // latent base

    // ---- load resident W slice (fp16 single, 64 KB) ----
    #pragma unroll
    for (int i = 0; i < 16; i++) {
        int e = tid + i * 256;             // 4096 x 16B
        int row = e >> 7, seg = e & 127;
        const __half* src = g_wr + (size_t)(r0 + row) * DLAT + seg * 8;
        CP16(sb + row * WROW + seg * 16, src);
    }
    CP_COMMIT();

    #define GX_PREF(T) do {                                                      \
        const float* gxt = g_gx + (size_t)(T) * BATCH * NGATE;                   \
        _Pragma("unroll")                                                        \
        for (int i = 0; i < 2; i++) {                                            \
            int e = tid + i * 256;                                               \
            int m = e >> 3, g = (e >> 1) & 3, half = e & 1;                      \
            const float* src = gxt + (size_t)m * NGATE + g * 1024 + jb + half * 4; \
            CP16(sb + GXBASE + m * 144 + g * 32 + half * 16, src);               \
        }                                                                        \
        CP_COMMIT();                                                             \
    } while (0)

    GX_PREF(0);
    CP_WAIT(0);
    __syncthreads();

    // ldmatrix lane-row pattern (A and B): lane&15 row, lane>>4 k-half
    const uint32_t lrow   = (uint32_t)(lane & 15);
    const uint32_t khalf  = (uint32_t)((lane >> 4) & 1) * 16;
    const uint32_t abase  = sb + (wm * 16 + lrow) * WROW + khalf;      // + k*2
    const uint32_t bbase0 = (wn * 32 + lrow) * BROW + khalf;           // group g: +g*16*BROW

    // epilogue ownership: cell pair (em, jb+ejl), (em, jb+ejl+1)
    const int em  = tid >> 2;
    const int ejl = (tid & 3) * 2;

    float creg[2] = {0.0f, 0.0f};
    float* red = (float*)(dsm + REDBASE);
    const float* gxs = (const float*)(dsm + GXBASE);

    for (int t = 0; t < SEQ; t++) {
        // ---- grid barrier (flags + block0 aggregator + epoch) ----
        if (t > 0) {
            if (tid == 0) st_rel(&g_flags[blockIdx.x], (unsigned)t);
            if (blockIdx.x == 0) {
                if (tid < 128) {
                    while (ld_acq(&g_flags[tid]) < (unsigned)t) {}
                }
                __syncthreads();
                if (tid == 0) st_rel(&g_epoch2, (unsigned)t);
            }
            if (tid == 0) {
                while (ld_acq(&g_epoch2) < (unsigned)t) {}
            }
            __syncthreads();
        }

        const int rb = t & 1;
        const __half* hsrc = g_h2[rb];

        // fill B chunk C (128 k, single fp16) into buf C&3: 4 CP16/thread
        #define FILL_B(C) do {                                                   \
            _Pragma("unroll")                                                    \
            for (int i = 0; i < 4; i++) {                                        \
                int e = tid + i * 256;                                           \
                int row = e >> 4, seg = e & 15;                                  \
                const __half* src = hsrc + (size_t)row * DLAT + (C) * 128 + seg * 8; \
                CP16(sb + BBASE + ((C) & 3) * BBUF + row * BROW + seg * 16, src); \
            }                                                                    \
            CP_COMMIT();                                                         \
        } while (0)

        FILL_B(0);
        FILL_B(1);
        FILL_B(2);
        FILL_B(3);

        float aH[4][4];
        #pragma unroll
        for (int nt = 0; nt < 4; nt++)
            #pragma unroll
            for (int i = 0; i < 4; i++) aH[nt][i] = 0.f;

        #pragma unroll 1
        for (int c = 0; c < 8; c++) {
            if (c + 4 < 8) CP_WAIT(3);
            else if (c == 5) CP_WAIT(2);
            else if (c == 6) CP_WAIT(1);
            else if (c == 7) CP_WAIT(0);
            else CP_WAIT(3);               // c == 4
            __syncthreads();

            const uint32_t bB = sb + BBASE + (c & 3) * BBUF + bbase0;
            const uint32_t kA = (uint32_t)(c * 128 + kg * 64) * 2;   // A byte k-offset
            const uint32_t kB = (uint32_t)(kg * 64) * 2;             // B byte k-offset in chunk

            #pragma unroll
            for (int q = 0; q < 4; q++) {
                uint32_t aw0, aw1, aw2, aw3;
                const uint32_t aq = abase + kA + (uint32_t)q * 32;
                LDSM_X4(aw0, aw1, aw2, aw3, aq);

                #pragma unroll
                for (int g = 0; g < 2; g++) {
                    uint32_t bh0, bh1, bh2, bh3;
                    const uint32_t bq = bB + (uint32_t)g * 16 * BROW + kB + (uint32_t)q * 32;
                    LDSM_X4(bh0, bh1, bh2, bh3, bq);
                    mma_f16(aH[2 * g + 0], aw0, aw1, aw2, aw3, bh0, bh2);
                    mma_f16(aH[2 * g + 1], aw0, aw1, aw2, aw3, bh1, bh3);
                }
            }
            __syncthreads();
            if (c + 4 < 8) FILL_B(c + 4);
        }

        // ---- stage kg-partials to smem scratch [kg][32 rows][66] ----
        #pragma unroll
        for (int nt = 0; nt < 4; nt++) {
            int R0 = wm * 16 + gid;
            int C  = wn * 32 + nt * 8 + tig * 2;
            *(float2*)&red[kg * 2112 + R0 * 66 + C]       = make_float2(aH[nt][0], aH[nt][1]);
            *(float2*)&red[kg * 2112 + (R0 + 8) * 66 + C] = make_float2(aH[nt][2], aH[nt][3]);
        }
        __syncthreads();

        // ---- fused epilogue: 2 cells per thread ----
        const int rb2 = rb ^ 1;
        __half* hw = g_h2[rb2];
        float hval[2];
        #pragma unroll
        for (int p = 0; p < 2; p++) {
            const int jl = ejl + p;
            const int rr = jl * 4;
            float sf = red[(rr + 0) * 66 + em] + red[2112 + (rr + 0) * 66 + em];
            float si = red[(rr + 1) * 66 + em] + red[2112 + (rr + 1) * 66 + em];
            float so = red[(rr + 2) * 66 + em] + red[2112 + (rr + 2) * 66 + em];
            float sg = red[(rr + 3) * 66 + em] + red[2112 + (rr + 3) * 66 + em];
            float vf = sigmoidf_(sf + gxs[em * 36 + 0 * 8 + jl]);
            float vi = sigmoidf_(si + gxs[em * 36 + 1 * 8 + jl]);
            float vo = sigmoidf_(so + gxs[em * 36 + 2 * 8 + jl]);
            float vg = tanhf_(sg + gxs[em * 36 + 3 * 8 + jl]);
            float cc = vf * creg[p] + vi * vg;
            creg[p] = cc;
            float h = vo * tanhf_(cc);
            hval[p] = h;
            const int j = jb + jl;
            hw[(size_t)em * DLAT + j] = __float2half(h);
        }
        *(float2*)&out[((size_t)t * BATCH + em) * DLAT + jb + ejl] =
            make_float2(hval[0], hval[1]);

        __syncthreads();
        if (t + 1 < SEQ) GX_PREF(t + 1);
    }
}

// ---------------------------------------------------------------
extern "C" void kernel_launch(void* const* d_in, const int* in_sizes, int n_in,
                              void* d_out, int out_size)
{
    const float* x  = (const float*)d_in[0];
    const float* Wf = (const float*)d_in[1];
    const float* bf = (const float*)d_in[2];
    const float* Wi = (const float*)d_in[3];
    const float* bi = (const float*)d_in[4];
    const float* Wo = (const float*)d_in[5];
    const float* bo = (const float*)d_in[6];
    const float* Wc = (const float*)d_in[7];
    const float* bc = (const float*)d_in[8];
    float* out = (float*)d_out;

    cudaFuncSetAttribute(input_hmma, cudaFuncAttributeMaxDynamicSharedMemorySize,
                         IA_DSMEM);
    cudaFuncSetAttribute(lstm_persistent, cudaFuncAttributeMaxDynamicSharedMemorySize,
                         DSMEM_BYTES);

    init_state<<<256, 256>>>();
    wsplit_build<<<(NGATE * DCAT) / 256, 256>>>(Wf, Wi, Wo, Wc);
    xsplit_build<<<(SEQ * BATCH * DIN) / (4 * 256), 256>>>(x);

    dim3 gridA(NGATE / 128, (SEQ * BATCH) / 128);   // (32, 256)
    input_hmma<<<gridA, 256, IA_DSMEM>>>(bf, bi, bo, bc);

    lstm_persistent<<<128, 256, DSMEM_BYTES>>>(out);
}